// round 13
// baseline (speedup 1.0000x reference)
#include <cuda_runtime.h>
#include <cuda_fp16.h>
#include <math.h>
#include <stdint.h>

// ---------------------------------------------------------------------------
// Problem constants
// ---------------------------------------------------------------------------
#define B_   8
#define C_   128
#define N_   4096
#define EPSN 1e-12f
// exp(x/0.1) = 2^(x * 10*log2(e)); fold sqrt of scale into both vectors.
#define ALPHA 3.7982826f          // sqrt(14.4269504089)

#define TM   128
#define GRIDP 148                 // persistent CTAs
// Work units: full 4-tile chunks first (8*112), then partial diag chunks (8*32)
#define NFULL  896
#define NUNITS 1152

// Scratch: normalized+scaled features fp16, [b][n][c] (8 MB)
__device__ __align__(16) __half g_vh[(size_t)B_ * N_ * C_];
// Per-row partial sums
__device__ float g_pos[B_ * N_];
__device__ float g_tot[B_ * N_];
// Dynamic work counter
__device__ int g_ctr;

// ---------------------------------------------------------------------------
// Helpers
// ---------------------------------------------------------------------------
__device__ __forceinline__ uint32_t smem_u32(const void* p) {
    uint32_t a;
    asm("{ .reg .u64 t; cvta.to.shared.u64 t, %1; cvt.u32.u64 %0, t; }"
        : "=r"(a) : "l"(p));
    return a;
}

__device__ __forceinline__ float ex2f(float x) {
    float y;
    asm("ex2.approx.f32 %0, %1;" : "=f"(y) : "f"(x));
    return y;
}

#define LDSM4(R0, R1, R2, R3, ADDR) \
    asm volatile("ldmatrix.sync.aligned.m8n8.x4.shared.b16 {%0,%1,%2,%3}, [%4];" \
                 : "=r"(R0), "=r"(R1), "=r"(R2), "=r"(R3) : "r"(ADDR))

#define MMA16816(AC, A0, A1, A2, A3, Bv0, Bv1) \
    asm volatile("mma.sync.aligned.m16n8k16.row.col.f32.f16.f16.f32 " \
                 "{%0,%1,%2,%3}, {%4,%5,%6,%7}, {%8,%9}, {%0,%1,%2,%3};" \
                 : "+f"((AC)[0]), "+f"((AC)[1]), "+f"((AC)[2]), "+f"((AC)[3]) \
                 : "r"(A0), "r"(A1), "r"(A2), "r"(A3), "r"(Bv0), "r"(Bv1))

#define CP_ASYNC16(DST, SRC) \
    asm volatile("cp.async.cg.shared.global [%0], [%1], 16;" :: "r"(DST), "l"(SRC))
#define CP_COMMIT()  asm volatile("cp.async.commit_group;" ::: "memory")
#define CP_WAIT0()   asm volatile("cp.async.wait_group 0;" ::: "memory")

// ---------------------------------------------------------------------------
// Unit decode.
//  w < NFULL : full chunks (len 4, no diagonal). b = w/112.
//              Within batch: rows grouped by g = rt>>2; chunks j in [1, 8-g).
//  w >= NFULL: partial diag chunks. b = (w-NFULL)/32, rt = (w-NFULL)%32,
//              c0 = rt (tile 0 is the diagonal), len = 4 - (rt&3).
// ---------------------------------------------------------------------------
__device__ __forceinline__ void decode_u(int w, int& b, int& rt,
                                         int& c0, int& len) {
    if (w < NFULL) {
        b = w / 112;
        int p = w - b * 112;
        int g = 0, cum = 0;
        while (p >= cum + 4 * (7 - g)) { cum += 4 * (7 - g); g++; }
        int idx = p - cum;
        int nj = 7 - g;
        int rowin = idx / nj, j = idx - rowin * nj + 1;
        rt = 4 * g + rowin;
        c0 = (g + j) * 4;
        len = 4;
    } else {
        int q = w - NFULL;
        b = q >> 5;
        rt = q & 31;
        c0 = rt;
        len = 4 - (rt & 3);
    }
}

// ---------------------------------------------------------------------------
// Kernel 1: normalize + scale by ALPHA + transpose -> fp16 [b][n][c].
// Also zeroes g_pos/g_tot, the work counter, and the output scalar.
// ---------------------------------------------------------------------------
__global__ void normalize_kernel(const float* __restrict__ feat,
                                 float* __restrict__ out) {
    __shared__ float t[C_][33];
    __shared__ float invn[32];
    const int b = blockIdx.y, n0 = blockIdx.x * 32, tid = threadIdx.x;
    const float* fb = feat + (size_t)b * C_ * N_;

    if (tid < 32) {
        g_pos[b * N_ + n0 + tid] = 0.0f;
        g_tot[b * N_ + n0 + tid] = 0.0f;
    }
    if (b == 0 && n0 == 0) {
        if (tid == 32) out[0] = 0.0f;
        if (tid == 33) g_ctr = 0;
    }

    for (int idx = tid; idx < C_ * 32; idx += 256) {
        int c = idx >> 5, nl = idx & 31;
        t[c][nl] = fb[(size_t)c * N_ + n0 + nl];
    }
    __syncthreads();

    const int w = tid >> 5, lane = tid & 31;
    #pragma unroll
    for (int p = 0; p < 4; p++) {
        int nl = w * 4 + p;
        float v0 = t[lane][nl], v1 = t[lane + 32][nl];
        float v2 = t[lane + 64][nl], v3 = t[lane + 96][nl];
        float s = v0 * v0 + v1 * v1 + v2 * v2 + v3 * v3;
        #pragma unroll
        for (int o = 16; o > 0; o >>= 1) s += __shfl_xor_sync(0xffffffffu, s, o);
        if (lane == 0) invn[nl] = ALPHA / fmaxf(sqrtf(s), EPSN);
    }
    __syncthreads();

    __half* vb = g_vh + ((size_t)b * N_ + n0) * C_;
    for (int idx = tid; idx < 32 * C_; idx += 256) {
        int nl = idx >> 7, c = idx & 127;
        vb[(size_t)nl * C_ + c] = __float2half(t[c][nl] * invn[nl]);
    }
}

// ---------------------------------------------------------------------------
// Tile copy: 128 rows x 256B (fp16) global -> swizzled smem via cp.async.
// ---------------------------------------------------------------------------
__device__ __forceinline__ void cp_tile(uint32_t sbase,
                                        const __half* __restrict__ src,
                                        int tid) {
    #pragma unroll
    for (int it = 0; it < 8; it++) {
        int idx = tid + it * 256;
        int r = idx >> 4, c = idx & 15;
        uint32_t dst = sbase + (uint32_t)r * 256u + (uint32_t)((c ^ (r & 7)) << 4);
        const char* g = (const char*)src + (size_t)r * 256 + c * 16;
        CP_ASYNC16(dst, g);
    }
}

// ---------------------------------------------------------------------------
// Half-tile K-loop: 32 rows x 32 cols x K=128 -> acc[2][4][4].
// ---------------------------------------------------------------------------
__device__ __forceinline__ void khalf(float (&acc)[2][4][4],
                                      const uint32_t (&af)[2][8][4],
                                      uint32_t sB,
                                      uint32_t bRow0, int bR70,
                                      uint32_t bRow1, int bR71, int csB) {
    #pragma unroll
    for (int mt = 0; mt < 2; mt++)
        #pragma unroll
        for (int nt = 0; nt < 4; nt++)
            #pragma unroll
            for (int q = 0; q < 4; q++) acc[mt][nt][q] = 0.0f;

    #pragma unroll
    for (int k = 0; k < 8; k++) {
        uint32_t bf0[4], bf1[4];
        LDSM4(bf0[0], bf0[1], bf0[2], bf0[3],
              sB + bRow0 + (uint32_t)(((2 * k + csB) ^ bR70) << 4));
        LDSM4(bf1[0], bf1[1], bf1[2], bf1[3],
              sB + bRow1 + (uint32_t)(((2 * k + csB) ^ bR71) << 4));
        #pragma unroll
        for (int mt = 0; mt < 2; mt++) {
            MMA16816(acc[mt][0], af[mt][k][0], af[mt][k][1], af[mt][k][2],
                     af[mt][k][3], bf0[0], bf0[1]);
            MMA16816(acc[mt][1], af[mt][k][0], af[mt][k][1], af[mt][k][2],
                     af[mt][k][3], bf0[2], bf0[3]);
            MMA16816(acc[mt][2], af[mt][k][0], af[mt][k][1], af[mt][k][2],
                     af[mt][k][3], bf1[0], bf1[1]);
            MMA16816(acc[mt][3], af[mt][k][0], af[mt][k][1], af[mt][k][2],
                     af[mt][k][3], bf1[2], bf1[3]);
        }
    }
}

// ---------------------------------------------------------------------------
// Epilogue, off-diagonal tile: rows AND columns credited.
// t = tile index within unit (cmask word base t*4, col smem base t*128).
// ---------------------------------------------------------------------------
__device__ __forceinline__ void epi_off(const float (&acc)[2][4][4],
                                        int t, int h,
                                        const unsigned* __restrict__ cmask,
                                        const int (&labr)[2][2],
                                        int warpN, int lane,
                                        float (&pos)[4], float (&tot)[4],
                                        float* __restrict__ colP_s,
                                        float* __restrict__ colT_s) {
    const int coff = warpN + h * 32;
    const int lw = t * 4 + (coff >> 5);
    float colT[4][2], colP[4][2];
    #pragma unroll
    for (int n = 0; n < 4; n++) {
        colT[n][0] = colT[n][1] = 0.f;
        colP[n][0] = colP[n][1] = 0.f;
    }
    #pragma unroll
    for (int mt = 0; mt < 2; mt++) {
        const unsigned w0 = cmask[labr[mt][0] * 16 + lw];
        const unsigned w1 = cmask[labr[mt][1] * 16 + lw];
        float t0 = 0.f, t1 = 0.f, p0 = 0.f, p1 = 0.f;
        #pragma unroll
        for (int ntl = 0; ntl < 4; ntl++) {
            const int sh = ntl * 8 + 2 * (lane & 3);
            const unsigned b0 = w0 >> sh;
            const unsigned b1 = w1 >> sh;
            float e00 = ex2f(acc[mt][ntl][0]);
            float e01 = ex2f(acc[mt][ntl][1]);
            float e10 = ex2f(acc[mt][ntl][2]);
            float e11 = ex2f(acc[mt][ntl][3]);
            float m00 = (b0 & 1u) ? e00 : 0.f;
            float m01 = (b0 & 2u) ? e01 : 0.f;
            float m10 = (b1 & 1u) ? e10 : 0.f;
            float m11 = (b1 & 2u) ? e11 : 0.f;
            t0 += e00 + e01;  t1 += e10 + e11;
            p0 += m00 + m01;  p1 += m10 + m11;
            colT[ntl][0] += e00 + e10;  colT[ntl][1] += e01 + e11;
            colP[ntl][0] += m00 + m10;  colP[ntl][1] += m01 + m11;
        }
        tot[mt * 2 + 0] += t0;  tot[mt * 2 + 1] += t1;
        pos[mt * 2 + 0] += p0;  pos[mt * 2 + 1] += p1;
    }
    // column reduce over the 8 row-lane-groups (lane bits 2,3,4)
    const int cbs = t * 128 + coff;
    #pragma unroll
    for (int ntl = 0; ntl < 4; ntl++) {
        #pragma unroll
        for (int par = 0; par < 2; par++) {
            float vT = colT[ntl][par], vP = colP[ntl][par];
            vT += __shfl_xor_sync(0xffffffffu, vT, 4);
            vT += __shfl_xor_sync(0xffffffffu, vT, 8);
            vT += __shfl_xor_sync(0xffffffffu, vT, 16);
            vP += __shfl_xor_sync(0xffffffffu, vP, 4);
            vP += __shfl_xor_sync(0xffffffffu, vP, 8);
            vP += __shfl_xor_sync(0xffffffffu, vP, 16);
            if (lane < 4) {
                int c = cbs + ntl * 8 + 2 * lane + par;
                atomicAdd(&colT_s[c], vT);
                atomicAdd(&colP_s[c], vP);
            }
        }
    }
}

// ---------------------------------------------------------------------------
// Epilogue, diagonal tile (ct == rt): rows only, zero the self column.
// ---------------------------------------------------------------------------
__device__ __forceinline__ void epi_diag(const float (&acc)[2][4][4],
                                         int t, int h,
                                         const unsigned* __restrict__ cmask,
                                         const int (&labr)[2][2],
                                         const int (&growb)[2],
                                         int warpN, int lane, int ct,
                                         float (&pos)[4], float (&tot)[4]) {
    const int coff = warpN + h * 32;
    const int lw = t * 4 + (coff >> 5);
    const int cb = ct * TM + coff;
    #pragma unroll
    for (int mt = 0; mt < 2; mt++) {
        const unsigned w0 = cmask[labr[mt][0] * 16 + lw];
        const unsigned w1 = cmask[labr[mt][1] * 16 + lw];
        const int g0 = growb[mt], g1 = growb[mt] + 8;
        float t0 = 0.f, t1 = 0.f, p0 = 0.f, p1 = 0.f;
        #pragma unroll
        for (int ntl = 0; ntl < 4; ntl++) {
            const int sh = ntl * 8 + 2 * (lane & 3);
            const unsigned b0 = w0 >> sh;
            const unsigned b1 = w1 >> sh;
            float e00 = ex2f(acc[mt][ntl][0]);
            float e01 = ex2f(acc[mt][ntl][1]);
            float e10 = ex2f(acc[mt][ntl][2]);
            float e11 = ex2f(acc[mt][ntl][3]);
            const int gc = cb + ntl * 8 + 2 * (lane & 3);
            if (g0 == gc)     e00 = 0.f;
            if (g0 == gc + 1) e01 = 0.f;
            if (g1 == gc)     e10 = 0.f;
            if (g1 == gc + 1) e11 = 0.f;
            t0 += e00 + e01;
            t1 += e10 + e11;
            p0 += ((b0 & 1u) ? e00 : 0.f) + ((b0 & 2u) ? e01 : 0.f);
            p1 += ((b1 & 1u) ? e10 : 0.f) + ((b1 & 2u) ? e11 : 0.f);
        }
        tot[mt * 2 + 0] += t0;  tot[mt * 2 + 1] += t1;
        pos[mt * 2 + 0] += p0;  pos[mt * 2 + 1] += p1;
    }
}

// ---------------------------------------------------------------------------
// Kernel 2: persistent symmetric HMMA GEMM, dynamic work queue, pipelined
// epilogue. Unit = (b, rt, up to 4 column tiles at/above the diagonal).
// Dyn smem: A 32K | B0 32K | B1 32K | cmask 1K | colP 2K | colT 2K |
//           posS 1K | totS 1K = 103 KB
// ---------------------------------------------------------------------------
#define SM_B0    32768
#define SM_B1    65536
#define SM_CMASK 98304
#define SM_COLP  (SM_CMASK + 1024)
#define SM_COLT  (SM_COLP + 2048)
#define SM_POSS  (SM_COLT + 2048)
#define SM_TOTS  (SM_POSS + 1024)
#define SM_DYN   (SM_TOTS + 1024)

__global__ void __launch_bounds__(256, 1)
loss_kernel(const int* __restrict__ labels) {
    extern __shared__ char sm[];
    __shared__ int u_s, un_s;

    const int tid = threadIdx.x, wid = tid >> 5, lane = tid & 31;

    unsigned* cmask = (unsigned*)(sm + SM_CMASK);   // [16 classes][16 words]
    float* colP_s = (float*)(sm + SM_COLP);         // [512]
    float* colT_s = (float*)(sm + SM_COLT);         // [512]
    float* posS   = (float*)(sm + SM_POSS);         // [128][2]
    float* totS   = (float*)(sm + SM_TOTS);

    const uint32_t sA = smem_u32(sm);
    const uint32_t sBb[2] = { smem_u32(sm + SM_B0), smem_u32(sm + SM_B1) };

    const int warpM = (wid & 3) * 32;
    const int warpN = (wid >> 2) * 64;

    // ldmatrix per-lane address components
    const int rA  = warpM + (lane & 15);
    const int csA = lane >> 4;
    const int rBl = (lane & 7) + ((lane & 16) >> 1);
    const int csB = (lane >> 3) & 1;

    uint32_t bRow[4];
    int bR7[4];
    #pragma unroll
    for (int np = 0; np < 4; np++) {
        int row = warpN + np * 16 + rBl;
        bRow[np] = (uint32_t)row * 256u;
        bR7[np] = row & 7;
    }

    // first unit grab + prologue loads
    if (tid == 0) u_s = atomicAdd(&g_ctr, 1);
    __syncthreads();
    int u = u_s;
    int pb = 0;
    if (u < NUNITS) {
        int b, rt, c0, len;
        decode_u(u, b, rt, c0, len);
        const __half* vb = g_vh + (size_t)b * N_ * C_;
        cp_tile(sA, vb + (size_t)(rt * TM) * C_, tid);
        cp_tile(sBb[0], vb + (size_t)(c0 * TM) * C_, tid);
        CP_COMMIT();
    }

    while (u < NUNITS) {
        int b, rt, c0, len;
        decode_u(u, b, rt, c0, len);
        const int* lb = labels + b * N_;
        const __half* vb = g_vh + (size_t)b * N_ * C_;

        if (tid == 0) un_s = atomicAdd(&g_ctr, 1);

        CP_WAIT0();
        __syncthreads();    // A + B0 ready; prev unit flush done; un_s visible
        const int un = un_s;

        // zero column accumulators
        for (int i = tid; i < 512; i += 256) {
            colP_s[i] = 0.0f;
            colT_s[i] = 0.0f;
        }

        // per-class column bitmasks for this unit's columns
        for (int w = wid; w < len * 4; w += 8) {
            int lab = lb[c0 * TM + w * 32 + lane];
            #pragma unroll
            for (int c = 0; c < 16; c++) {
                unsigned m = __ballot_sync(0xffffffffu, lab == c);
                if (lane == c) cmask[c * 16 + w] = m;
            }
        }

        // row identities
        int growb[2], labr[2][2];
        #pragma unroll
        for (int mt = 0; mt < 2; mt++) {
            growb[mt] = rt * TM + warpM + mt * 16 + (lane >> 2);
            labr[mt][0] = lb[growb[mt]];
            labr[mt][1] = lb[growb[mt] + 8];
        }

        // A fragments cached in registers for the whole unit
        uint32_t af[2][8][4];
        #pragma unroll
        for (int mt = 0; mt < 2; mt++) {
            int row = rA + mt * 16;
            uint32_t base = sA + (uint32_t)row * 256u;
            int r7 = row & 7;
            #pragma unroll
            for (int k = 0; k < 8; k++) {
                uint32_t addr = base + (uint32_t)(((2 * k + csA) ^ r7) << 4);
                LDSM4(af[mt][k][0], af[mt][k][1], af[mt][k][2], af[mt][k][3],
                      addr);
            }
        }
        __syncthreads();    // cmask + col zeros visible; af loads done

        float pos[4] = {0.f, 0.f, 0.f, 0.f};
        float tot[4] = {0.f, 0.f, 0.f, 0.f};
        float acc0[2][4][4], acc1[2][4][4];

        for (int t = 0; t < len; t++) {
            const uint32_t sB = sBb[(pb + t) & 1];
            if (t + 1 < len) {
                cp_tile(sBb[(pb + t + 1) & 1],
                        vb + (size_t)((c0 + t + 1) * TM) * C_, tid);
                CP_COMMIT();
            } else if (un < NUNITS) {
                int bn, rtn, c0n, lenn;
                decode_u(un, bn, rtn, c0n, lenn);
                const __half* vbn = g_vh + (size_t)bn * N_ * C_;
                cp_tile(sA, vbn + (size_t)(rtn * TM) * C_, tid);
                cp_tile(sBb[(pb + len) & 1],
                        vbn + (size_t)(c0n * TM) * C_, tid);
                CP_COMMIT();
            }

            // pipelined: K0(t), E1(t-1), K1(t), E0(t)
            khalf(acc0, af, sB, bRow[0], bR7[0], bRow[1], bR7[1], csB);
            if (t > 0) {
                if (c0 + t - 1 == rt)
                    epi_diag(acc1, t - 1, 1, cmask, labr, growb, warpN, lane,
                             c0 + t - 1, pos, tot);
                else
                    epi_off(acc1, t - 1, 1, cmask, labr, warpN, lane,
                            pos, tot, colP_s, colT_s);
            }
            khalf(acc1, af, sB, bRow[2], bR7[2], bRow[3], bR7[3], csB);
            if (c0 + t == rt)
                epi_diag(acc0, t, 0, cmask, labr, growb, warpN, lane,
                         c0 + t, pos, tot);
            else
                epi_off(acc0, t, 0, cmask, labr, warpN, lane,
                        pos, tot, colP_s, colT_s);

            CP_WAIT0();
            __syncthreads();
        }
        // flush pending last half
        if (c0 + len - 1 == rt)
            epi_diag(acc1, len - 1, 1, cmask, labr, growb, warpN, lane,
                     c0 + len - 1, pos, tot);
        else
            epi_off(acc1, len - 1, 1, cmask, labr, warpN, lane,
                    pos, tot, colP_s, colT_s);

        // row merge: reduce 4 lanes per row, merge 2 N-warps via smem
        #pragma unroll
        for (int q = 0; q < 4; q++) {
            pos[q] += __shfl_xor_sync(0xffffffffu, pos[q], 1);
            pos[q] += __shfl_xor_sync(0xffffffffu, pos[q], 2);
            tot[q] += __shfl_xor_sync(0xffffffffu, tot[q], 1);
            tot[q] += __shfl_xor_sync(0xffffffffu, tot[q], 2);
        }
        const int widN = wid >> 2;
        if ((lane & 3) == 0) {
            #pragma unroll
            for (int mt = 0; mt < 2; mt++) {
                int rl = warpM + mt * 16 + (lane >> 2);
                posS[rl * 2 + widN]       = pos[mt * 2 + 0];
                totS[rl * 2 + widN]       = tot[mt * 2 + 0];
                posS[(rl + 8) * 2 + widN] = pos[mt * 2 + 1];
                totS[(rl + 8) * 2 + widN] = tot[mt * 2 + 1];
            }
        }
        __syncthreads();    // posS/totS + all col atomics complete

        // flush rows (always) and columns (diag part of colP/colT is zero)
        if (tid < TM) {
            float P = posS[tid * 2] + posS[tid * 2 + 1];
            float T = totS[tid * 2] + totS[tid * 2 + 1];
            atomicAdd(&g_pos[b * N_ + rt * TM + tid], P);
            atomicAdd(&g_tot[b * N_ + rt * TM + tid], T);
        }
        for (int i = tid; i < len * TM; i += 256) {
            atomicAdd(&g_pos[b * N_ + c0 * TM + i], colP_s[i]);
            atomicAdd(&g_tot[b * N_ + c0 * TM + i], colT_s[i]);
        }

        u = un;
        pb = (pb + len) & 1;
    }
}

// ---------------------------------------------------------------------------
// Kernel 3: finalize — dev = log(T) - log(P) per row, mean into out.
// ---------------------------------------------------------------------------
__global__ void finalize_kernel(float* __restrict__ out) {
    __shared__ float ws[8];
    const int idx = blockIdx.x * 256 + threadIdx.x;
    const int lane = threadIdx.x & 31, wid = threadIdx.x >> 5;
    float dev = __logf(g_tot[idx]) - __logf(g_pos[idx]);
    #pragma unroll
    for (int o = 16; o > 0; o >>= 1) dev += __shfl_xor_sync(0xffffffffu, dev, o);
    if (lane == 0) ws[wid] = dev;
    __syncthreads();
    if (threadIdx.x == 0) {
        float s = 0.0f;
        #pragma unroll
        for (int w = 0; w < 8; w++) s += ws[w];
        atomicAdd(out, s * (1.0f / ((float)B_ * (float)N_)));
    }
}

// ---------------------------------------------------------------------------
// Launch
// ---------------------------------------------------------------------------
extern "C" void kernel_launch(void* const* d_in, const int* in_sizes, int n_in,
                              void* d_out, int out_size) {
    const float* feat   = (const float*)d_in[0];
    const int*   labels = (const int*)d_in[1];
    float*       out    = (float*)d_out;

    dim3 gn(N_ / 32, B_);
    normalize_kernel<<<gn, 256>>>(feat, out);

    cudaFuncSetAttribute(loss_kernel,
                         cudaFuncAttributeMaxDynamicSharedMemorySize, SM_DYN);
    loss_kernel<<<GRIDP, 256, SM_DYN>>>(labels);

    finalize_kernel<<<(B_ * N_) / 256, 256>>>(out);
}

// round 14
// speedup vs baseline: 1.0713x; 1.0713x over previous
#include <cuda_runtime.h>
#include <cuda_fp16.h>
#include <math.h>
#include <stdint.h>

// ---------------------------------------------------------------------------
// Problem constants
// ---------------------------------------------------------------------------
#define B_   8
#define C_   128
#define N_   4096
#define EPSN 1e-12f
// exp(x/0.1) = 2^(x * 10*log2(e)); fold sqrt of scale into both vectors.
#define ALPHA 3.7982826f          // sqrt(14.4269504089)

#define TM   128
#define GRIDP 148                 // persistent CTAs
// Work units: full 4-tile chunks first (8*112), then partial diag chunks (8*32)
#define NFULL  896
#define NUNITS 1152

// Scratch: normalized+scaled features fp16, [b][n][c] (8 MB)
__device__ __align__(16) __half g_vh[(size_t)B_ * N_ * C_];
// Per-row partial sums
__device__ float g_pos[B_ * N_];
__device__ float g_tot[B_ * N_];
// Dynamic work counter
__device__ int g_ctr;

// ---------------------------------------------------------------------------
// Helpers
// ---------------------------------------------------------------------------
__device__ __forceinline__ uint32_t smem_u32(const void* p) {
    uint32_t a;
    asm("{ .reg .u64 t; cvta.to.shared.u64 t, %1; cvt.u32.u64 %0, t; }"
        : "=r"(a) : "l"(p));
    return a;
}

__device__ __forceinline__ float ex2f(float x) {
    float y;
    asm("ex2.approx.f32 %0, %1;" : "=f"(y) : "f"(x));
    return y;
}

#define LDSM4(R0, R1, R2, R3, ADDR) \
    asm volatile("ldmatrix.sync.aligned.m8n8.x4.shared.b16 {%0,%1,%2,%3}, [%4];" \
                 : "=r"(R0), "=r"(R1), "=r"(R2), "=r"(R3) : "r"(ADDR))

#define MMA16816(AC, A0, A1, A2, A3, Bv0, Bv1) \
    asm volatile("mma.sync.aligned.m16n8k16.row.col.f32.f16.f16.f32 " \
                 "{%0,%1,%2,%3}, {%4,%5,%6,%7}, {%8,%9}, {%0,%1,%2,%3};" \
                 : "+f"((AC)[0]), "+f"((AC)[1]), "+f"((AC)[2]), "+f"((AC)[3]) \
                 : "r"(A0), "r"(A1), "r"(A2), "r"(A3), "r"(Bv0), "r"(Bv1))

#define CP_ASYNC16(DST, SRC) \
    asm volatile("cp.async.cg.shared.global [%0], [%1], 16;" :: "r"(DST), "l"(SRC))
#define CP_COMMIT()  asm volatile("cp.async.commit_group;" ::: "memory")
#define CP_WAIT0()   asm volatile("cp.async.wait_group 0;" ::: "memory")

// ---------------------------------------------------------------------------
// Unit decode.
//  w < NFULL : full chunks (len 4, no diagonal). b = w/112.
//              Within batch: rows grouped by g = rt>>2; chunks j in [1, 8-g).
//  w >= NFULL: partial diag chunks. b = (w-NFULL)/32, rt = (w-NFULL)%32,
//              c0 = rt (tile 0 is the diagonal), len = 4 - (rt&3).
// ---------------------------------------------------------------------------
__device__ __forceinline__ void decode_u(int w, int& b, int& rt,
                                         int& c0, int& len) {
    if (w < NFULL) {
        b = w / 112;
        int p = w - b * 112;
        int g = 0, cum = 0;
        while (p >= cum + 4 * (7 - g)) { cum += 4 * (7 - g); g++; }
        int idx = p - cum;
        int nj = 7 - g;
        int rowin = idx / nj, j = idx - rowin * nj + 1;
        rt = 4 * g + rowin;
        c0 = (g + j) * 4;
        len = 4;
    } else {
        int q = w - NFULL;
        b = q >> 5;
        rt = q & 31;
        c0 = rt;
        len = 4 - (rt & 3);
    }
}

// ---------------------------------------------------------------------------
// Kernel 1: normalize + scale by ALPHA + transpose -> fp16 [b][n][c].
// Also zeroes g_pos/g_tot, the work counter, and the output scalar.
// ---------------------------------------------------------------------------
__global__ void normalize_kernel(const float* __restrict__ feat,
                                 float* __restrict__ out) {
    __shared__ float t[C_][33];
    __shared__ float invn[32];
    const int b = blockIdx.y, n0 = blockIdx.x * 32, tid = threadIdx.x;
    const float* fb = feat + (size_t)b * C_ * N_;

    if (tid < 32) {
        g_pos[b * N_ + n0 + tid] = 0.0f;
        g_tot[b * N_ + n0 + tid] = 0.0f;
    }
    if (b == 0 && n0 == 0) {
        if (tid == 32) out[0] = 0.0f;
        if (tid == 33) g_ctr = 0;
    }

    for (int idx = tid; idx < C_ * 32; idx += 256) {
        int c = idx >> 5, nl = idx & 31;
        t[c][nl] = fb[(size_t)c * N_ + n0 + nl];
    }
    __syncthreads();

    const int w = tid >> 5, lane = tid & 31;
    #pragma unroll
    for (int p = 0; p < 4; p++) {
        int nl = w * 4 + p;
        float v0 = t[lane][nl], v1 = t[lane + 32][nl];
        float v2 = t[lane + 64][nl], v3 = t[lane + 96][nl];
        float s = v0 * v0 + v1 * v1 + v2 * v2 + v3 * v3;
        #pragma unroll
        for (int o = 16; o > 0; o >>= 1) s += __shfl_xor_sync(0xffffffffu, s, o);
        if (lane == 0) invn[nl] = ALPHA / fmaxf(sqrtf(s), EPSN);
    }
    __syncthreads();

    __half* vb = g_vh + ((size_t)b * N_ + n0) * C_;
    for (int idx = tid; idx < 32 * C_; idx += 256) {
        int nl = idx >> 7, c = idx & 127;
        vb[(size_t)nl * C_ + c] = __float2half(t[c][nl] * invn[nl]);
    }
}

// ---------------------------------------------------------------------------
// Tile copy: 128 rows x 256B (fp16) global -> swizzled smem via cp.async.
// ---------------------------------------------------------------------------
__device__ __forceinline__ void cp_tile(uint32_t sbase,
                                        const __half* __restrict__ src,
                                        int tid) {
    #pragma unroll
    for (int it = 0; it < 8; it++) {
        int idx = tid + it * 256;
        int r = idx >> 4, c = idx & 15;
        uint32_t dst = sbase + (uint32_t)r * 256u + (uint32_t)((c ^ (r & 7)) << 4);
        const char* g = (const char*)src + (size_t)r * 256 + c * 16;
        CP_ASYNC16(dst, g);
    }
}

// ---------------------------------------------------------------------------
// Half-tile K-loop: 32 rows x 32 cols x K=128 -> acc[2][4][4].
// ---------------------------------------------------------------------------
__device__ __forceinline__ void khalf(float (&acc)[2][4][4],
                                      const uint32_t (&af)[2][8][4],
                                      uint32_t sB,
                                      uint32_t bRow0, int bR70,
                                      uint32_t bRow1, int bR71, int csB) {
    #pragma unroll
    for (int mt = 0; mt < 2; mt++)
        #pragma unroll
        for (int nt = 0; nt < 4; nt++)
            #pragma unroll
            for (int q = 0; q < 4; q++) acc[mt][nt][q] = 0.0f;

    #pragma unroll
    for (int k = 0; k < 8; k++) {
        uint32_t bf0[4], bf1[4];
        LDSM4(bf0[0], bf0[1], bf0[2], bf0[3],
              sB + bRow0 + (uint32_t)(((2 * k + csB) ^ bR70) << 4));
        LDSM4(bf1[0], bf1[1], bf1[2], bf1[3],
              sB + bRow1 + (uint32_t)(((2 * k + csB) ^ bR71) << 4));
        #pragma unroll
        for (int mt = 0; mt < 2; mt++) {
            MMA16816(acc[mt][0], af[mt][k][0], af[mt][k][1], af[mt][k][2],
                     af[mt][k][3], bf0[0], bf0[1]);
            MMA16816(acc[mt][1], af[mt][k][0], af[mt][k][1], af[mt][k][2],
                     af[mt][k][3], bf0[2], bf0[3]);
            MMA16816(acc[mt][2], af[mt][k][0], af[mt][k][1], af[mt][k][2],
                     af[mt][k][3], bf1[0], bf1[1]);
            MMA16816(acc[mt][3], af[mt][k][0], af[mt][k][1], af[mt][k][2],
                     af[mt][k][3], bf1[2], bf1[3]);
        }
    }
}

// ---------------------------------------------------------------------------
// Epilogue, off-diagonal tile: rows AND columns credited.
// t = tile index within unit (cmask word base t*4, col smem base t*128).
// ---------------------------------------------------------------------------
__device__ __forceinline__ void epi_off(const float (&acc)[2][4][4],
                                        int t, int h,
                                        const unsigned* __restrict__ cmask,
                                        const int (&labr)[2][2],
                                        int warpN, int lane,
                                        float (&pos)[4], float (&tot)[4],
                                        float* __restrict__ colP_s,
                                        float* __restrict__ colT_s) {
    const int coff = warpN + h * 32;
    const int lw = t * 4 + (coff >> 5);
    float colT[4][2], colP[4][2];
    #pragma unroll
    for (int n = 0; n < 4; n++) {
        colT[n][0] = colT[n][1] = 0.f;
        colP[n][0] = colP[n][1] = 0.f;
    }
    #pragma unroll
    for (int mt = 0; mt < 2; mt++) {
        const unsigned w0 = cmask[labr[mt][0] * 16 + lw];
        const unsigned w1 = cmask[labr[mt][1] * 16 + lw];
        float t0 = 0.f, t1 = 0.f, p0 = 0.f, p1 = 0.f;
        #pragma unroll
        for (int ntl = 0; ntl < 4; ntl++) {
            const int sh = ntl * 8 + 2 * (lane & 3);
            const unsigned b0 = w0 >> sh;
            const unsigned b1 = w1 >> sh;
            float e00 = ex2f(acc[mt][ntl][0]);
            float e01 = ex2f(acc[mt][ntl][1]);
            float e10 = ex2f(acc[mt][ntl][2]);
            float e11 = ex2f(acc[mt][ntl][3]);
            float m00 = (b0 & 1u) ? e00 : 0.f;
            float m01 = (b0 & 2u) ? e01 : 0.f;
            float m10 = (b1 & 1u) ? e10 : 0.f;
            float m11 = (b1 & 2u) ? e11 : 0.f;
            t0 += e00 + e01;  t1 += e10 + e11;
            p0 += m00 + m01;  p1 += m10 + m11;
            colT[ntl][0] += e00 + e10;  colT[ntl][1] += e01 + e11;
            colP[ntl][0] += m00 + m10;  colP[ntl][1] += m01 + m11;
        }
        tot[mt * 2 + 0] += t0;  tot[mt * 2 + 1] += t1;
        pos[mt * 2 + 0] += p0;  pos[mt * 2 + 1] += p1;
    }
    // column reduce over the 8 row-lane-groups (lane bits 2,3,4)
    const int cbs = t * 128 + coff;
    #pragma unroll
    for (int ntl = 0; ntl < 4; ntl++) {
        #pragma unroll
        for (int par = 0; par < 2; par++) {
            float vT = colT[ntl][par], vP = colP[ntl][par];
            vT += __shfl_xor_sync(0xffffffffu, vT, 4);
            vT += __shfl_xor_sync(0xffffffffu, vT, 8);
            vT += __shfl_xor_sync(0xffffffffu, vT, 16);
            vP += __shfl_xor_sync(0xffffffffu, vP, 4);
            vP += __shfl_xor_sync(0xffffffffu, vP, 8);
            vP += __shfl_xor_sync(0xffffffffu, vP, 16);
            if (lane < 4) {
                int c = cbs + ntl * 8 + 2 * lane + par;
                atomicAdd(&colT_s[c], vT);
                atomicAdd(&colP_s[c], vP);
            }
        }
    }
}

// ---------------------------------------------------------------------------
// Epilogue, diagonal tile (ct == rt): rows only, zero the self column.
// ---------------------------------------------------------------------------
__device__ __forceinline__ void epi_diag(const float (&acc)[2][4][4],
                                         int t, int h,
                                         const unsigned* __restrict__ cmask,
                                         const int (&labr)[2][2],
                                         const int (&growb)[2],
                                         int warpN, int lane, int ct,
                                         float (&pos)[4], float (&tot)[4]) {
    const int coff = warpN + h * 32;
    const int lw = t * 4 + (coff >> 5);
    const int cb = ct * TM + coff;
    #pragma unroll
    for (int mt = 0; mt < 2; mt++) {
        const unsigned w0 = cmask[labr[mt][0] * 16 + lw];
        const unsigned w1 = cmask[labr[mt][1] * 16 + lw];
        const int g0 = growb[mt], g1 = growb[mt] + 8;
        float t0 = 0.f, t1 = 0.f, p0 = 0.f, p1 = 0.f;
        #pragma unroll
        for (int ntl = 0; ntl < 4; ntl++) {
            const int sh = ntl * 8 + 2 * (lane & 3);
            const unsigned b0 = w0 >> sh;
            const unsigned b1 = w1 >> sh;
            float e00 = ex2f(acc[mt][ntl][0]);
            float e01 = ex2f(acc[mt][ntl][1]);
            float e10 = ex2f(acc[mt][ntl][2]);
            float e11 = ex2f(acc[mt][ntl][3]);
            const int gc = cb + ntl * 8 + 2 * (lane & 3);
            if (g0 == gc)     e00 = 0.f;
            if (g0 == gc + 1) e01 = 0.f;
            if (g1 == gc)     e10 = 0.f;
            if (g1 == gc + 1) e11 = 0.f;
            t0 += e00 + e01;
            t1 += e10 + e11;
            p0 += ((b0 & 1u) ? e00 : 0.f) + ((b0 & 2u) ? e01 : 0.f);
            p1 += ((b1 & 1u) ? e10 : 0.f) + ((b1 & 2u) ? e11 : 0.f);
        }
        tot[mt * 2 + 0] += t0;  tot[mt * 2 + 1] += t1;
        pos[mt * 2 + 0] += p0;  pos[mt * 2 + 1] += p1;
    }
}

// ---------------------------------------------------------------------------
// Kernel 2: persistent symmetric HMMA GEMM, dynamic work queue.
// SERIAL halves per warp (single acc set -> no register spills); cross-pipe
// overlap comes from 2 warps/SMSP running in natural antiphase.
// Dyn smem: A 32K | B0 32K | B1 32K | cmask 1K | colP 2K | colT 2K |
//           posS 1K | totS 1K = 103 KB
// ---------------------------------------------------------------------------
#define SM_B0    32768
#define SM_B1    65536
#define SM_CMASK 98304
#define SM_COLP  (SM_CMASK + 1024)
#define SM_COLT  (SM_COLP + 2048)
#define SM_POSS  (SM_COLT + 2048)
#define SM_TOTS  (SM_POSS + 1024)
#define SM_DYN   (SM_TOTS + 1024)

__global__ void __launch_bounds__(256, 1)
loss_kernel(const int* __restrict__ labels) {
    extern __shared__ char sm[];
    __shared__ int u_s, un_s;

    const int tid = threadIdx.x, wid = tid >> 5, lane = tid & 31;

    unsigned* cmask = (unsigned*)(sm + SM_CMASK);   // [16 classes][16 words]
    float* colP_s = (float*)(sm + SM_COLP);         // [512]
    float* colT_s = (float*)(sm + SM_COLT);         // [512]
    float* posS   = (float*)(sm + SM_POSS);         // [128][2]
    float* totS   = (float*)(sm + SM_TOTS);

    const uint32_t sA = smem_u32(sm);
    const uint32_t sBb[2] = { smem_u32(sm + SM_B0), smem_u32(sm + SM_B1) };

    const int warpM = (wid & 3) * 32;
    const int warpN = (wid >> 2) * 64;

    // ldmatrix per-lane address components
    const int rA  = warpM + (lane & 15);
    const int csA = lane >> 4;
    const int rBl = (lane & 7) + ((lane & 16) >> 1);
    const int csB = (lane >> 3) & 1;

    uint32_t bRow[4];
    int bR7[4];
    #pragma unroll
    for (int np = 0; np < 4; np++) {
        int row = warpN + np * 16 + rBl;
        bRow[np] = (uint32_t)row * 256u;
        bR7[np] = row & 7;
    }

    // first unit grab + prologue loads
    if (tid == 0) u_s = atomicAdd(&g_ctr, 1);
    __syncthreads();
    int u = u_s;
    int pb = 0;
    if (u < NUNITS) {
        int b, rt, c0, len;
        decode_u(u, b, rt, c0, len);
        const __half* vb = g_vh + (size_t)b * N_ * C_;
        cp_tile(sA, vb + (size_t)(rt * TM) * C_, tid);
        cp_tile(sBb[0], vb + (size_t)(c0 * TM) * C_, tid);
        CP_COMMIT();
    }

    while (u < NUNITS) {
        int b, rt, c0, len;
        decode_u(u, b, rt, c0, len);
        const int* lb = labels + b * N_;
        const __half* vb = g_vh + (size_t)b * N_ * C_;

        if (tid == 0) un_s = atomicAdd(&g_ctr, 1);

        CP_WAIT0();
        __syncthreads();    // A + B0 ready; prev unit flush done; un_s visible
        const int un = un_s;

        // zero column accumulators
        for (int i = tid; i < 512; i += 256) {
            colP_s[i] = 0.0f;
            colT_s[i] = 0.0f;
        }

        // per-class column bitmasks for this unit's columns
        for (int w = wid; w < len * 4; w += 8) {
            int lab = lb[c0 * TM + w * 32 + lane];
            #pragma unroll
            for (int c = 0; c < 16; c++) {
                unsigned m = __ballot_sync(0xffffffffu, lab == c);
                if (lane == c) cmask[c * 16 + w] = m;
            }
        }

        // row identities
        int growb[2], labr[2][2];
        #pragma unroll
        for (int mt = 0; mt < 2; mt++) {
            growb[mt] = rt * TM + warpM + mt * 16 + (lane >> 2);
            labr[mt][0] = lb[growb[mt]];
            labr[mt][1] = lb[growb[mt] + 8];
        }

        // A fragments cached in registers for the whole unit
        uint32_t af[2][8][4];
        #pragma unroll
        for (int mt = 0; mt < 2; mt++) {
            int row = rA + mt * 16;
            uint32_t base = sA + (uint32_t)row * 256u;
            int r7 = row & 7;
            #pragma unroll
            for (int k = 0; k < 8; k++) {
                uint32_t addr = base + (uint32_t)(((2 * k + csA) ^ r7) << 4);
                LDSM4(af[mt][k][0], af[mt][k][1], af[mt][k][2], af[mt][k][3],
                      addr);
            }
        }
        __syncthreads();    // cmask + col zeros visible; af loads done

        float pos[4] = {0.f, 0.f, 0.f, 0.f};
        float tot[4] = {0.f, 0.f, 0.f, 0.f};

        for (int t = 0; t < len; t++) {
            const uint32_t sB = sBb[(pb + t) & 1];
            if (t + 1 < len) {
                cp_tile(sBb[(pb + t + 1) & 1],
                        vb + (size_t)((c0 + t + 1) * TM) * C_, tid);
                CP_COMMIT();
            } else if (un < NUNITS) {
                int bn, rtn, c0n, lenn;
                decode_u(un, bn, rtn, c0n, lenn);
                const __half* vbn = g_vh + (size_t)bn * N_ * C_;
                cp_tile(sA, vbn + (size_t)(rtn * TM) * C_, tid);
                cp_tile(sBb[(pb + len) & 1],
                        vbn + (size_t)(c0n * TM) * C_, tid);
                CP_COMMIT();
            }

            const bool isDiag = (c0 + t == rt);   // uniform per tile
            float acc[2][4][4];                   // single live acc set

            khalf(acc, af, sB, bRow[0], bR7[0], bRow[1], bR7[1], csB);
            if (isDiag)
                epi_diag(acc, t, 0, cmask, labr, growb, warpN, lane,
                         c0 + t, pos, tot);
            else
                epi_off(acc, t, 0, cmask, labr, warpN, lane,
                        pos, tot, colP_s, colT_s);

            khalf(acc, af, sB, bRow[2], bR7[2], bRow[3], bR7[3], csB);
            if (isDiag)
                epi_diag(acc, t, 1, cmask, labr, growb, warpN, lane,
                         c0 + t, pos, tot);
            else
                epi_off(acc, t, 1, cmask, labr, warpN, lane,
                        pos, tot, colP_s, colT_s);

            CP_WAIT0();
            __syncthreads();
        }

        // row merge: reduce 4 lanes per row, merge 2 N-warps via smem
        #pragma unroll
        for (int q = 0; q < 4; q++) {
            pos[q] += __shfl_xor_sync(0xffffffffu, pos[q], 1);
            pos[q] += __shfl_xor_sync(0xffffffffu, pos[q], 2);
            tot[q] += __shfl_xor_sync(0xffffffffu, tot[q], 1);
            tot[q] += __shfl_xor_sync(0xffffffffu, tot[q], 2);
        }
        const int widN = wid >> 2;
        if ((lane & 3) == 0) {
            #pragma unroll
            for (int mt = 0; mt < 2; mt++) {
                int rl = warpM + mt * 16 + (lane >> 2);
                posS[rl * 2 + widN]       = pos[mt * 2 + 0];
                totS[rl * 2 + widN]       = tot[mt * 2 + 0];
                posS[(rl + 8) * 2 + widN] = pos[mt * 2 + 1];
                totS[(rl + 8) * 2 + widN] = tot[mt * 2 + 1];
            }
        }
        __syncthreads();    // posS/totS + all col atomics complete

        // flush rows (always) and columns (diag part of colP/colT is zero)
        if (tid < TM) {
            float P = posS[tid * 2] + posS[tid * 2 + 1];
            float T = totS[tid * 2] + totS[tid * 2 + 1];
            atomicAdd(&g_pos[b * N_ + rt * TM + tid], P);
            atomicAdd(&g_tot[b * N_ + rt * TM + tid], T);
        }
        for (int i = tid; i < len * TM; i += 256) {
            atomicAdd(&g_pos[b * N_ + c0 * TM + i], colP_s[i]);
            atomicAdd(&g_tot[b * N_ + c0 * TM + i], colT_s[i]);
        }

        u = un;
        pb = (pb + len) & 1;
    }
}

// ---------------------------------------------------------------------------
// Kernel 3: finalize — dev = log(T) - log(P) per row, mean into out.
// ---------------------------------------------------------------------------
__global__ void finalize_kernel(float* __restrict__ out) {
    __shared__ float ws[8];
    const int idx = blockIdx.x * 256 + threadIdx.x;
    const int lane = threadIdx.x & 31, wid = threadIdx.x >> 5;
    float dev = __logf(g_tot[idx]) - __logf(g_pos[idx]);
    #pragma unroll
    for (int o = 16; o > 0; o >>= 1) dev += __shfl_xor_sync(0xffffffffu, dev, o);
    if (lane == 0) ws[wid] = dev;
    __syncthreads();
    if (threadIdx.x == 0) {
        float s = 0.0f;
        #pragma unroll
        for (int w = 0; w < 8; w++) s += ws[w];
        atomicAdd(out, s * (1.0f / ((float)B_ * (float)N_)));
    }
}

// ---------------------------------------------------------------------------
// Launch
// ---------------------------------------------------------------------------
extern "C" void kernel_launch(void* const* d_in, const int* in_sizes, int n_in,
                              void* d_out, int out_size) {
    const float* feat   = (const float*)d_in[0];
    const int*   labels = (const int*)d_in[1];
    float*       out    = (float*)d_out;

    dim3 gn(N_ / 32, B_);
    normalize_kernel<<<gn, 256>>>(feat, out);

    cudaFuncSetAttribute(loss_kernel,
                         cudaFuncAttributeMaxDynamicSharedMemorySize, SM_DYN);
    loss_kernel<<<GRIDP, 256, SM_DYN>>>(labels);

    finalize_kernel<<<(B_ * N_) / 256, 256>>>(out);
}

// round 15
// speedup vs baseline: 1.3751x; 1.2836x over previous
#include <cuda_runtime.h>
#include <cuda_fp16.h>
#include <math.h>
#include <stdint.h>

// ---------------------------------------------------------------------------
// Problem constants
// ---------------------------------------------------------------------------
#define B_   8
#define C_   128
#define N_   4096
#define EPSN 1e-12f
// exp(x/0.1) = 2^(x * 10*log2(e)); fold sqrt of scale into both vectors.
#define ALPHA 3.7982826f          // sqrt(14.4269504089)

#define TM   128                  // rows per unit
#define TN   128                  // cols per iteration tile
#define IPU  8                    // iterations (col tiles) per unit
#define NU   (B_ * 32 * 4)        // 1024 work units
#define GRIDP 148                 // persistent CTAs

// Scratch: normalized+scaled features fp16, [b][n][c] (8 MB)
__device__ __align__(16) __half g_vh[(size_t)B_ * N_ * C_];
// Per-row partial sums (merged across col-quarter units)
__device__ float g_pos[B_ * N_];
__device__ float g_tot[B_ * N_];

// ---------------------------------------------------------------------------
// Helpers
// ---------------------------------------------------------------------------
__device__ __forceinline__ uint32_t smem_u32(const void* p) {
    uint32_t a;
    asm("{ .reg .u64 t; cvta.to.shared.u64 t, %1; cvt.u32.u64 %0, t; }"
        : "=r"(a) : "l"(p));
    return a;
}

__device__ __forceinline__ float ex2f(float x) {
    float y;
    asm("ex2.approx.f32 %0, %1;" : "=f"(y) : "f"(x));
    return y;
}

#define LDSM4(R0, R1, R2, R3, ADDR) \
    asm volatile("ldmatrix.sync.aligned.m8n8.x4.shared.b16 {%0,%1,%2,%3}, [%4];" \
                 : "=r"(R0), "=r"(R1), "=r"(R2), "=r"(R3) : "r"(ADDR))

#define MMA16816(AC, A0, A1, A2, A3, Bv0, Bv1) \
    asm volatile("mma.sync.aligned.m16n8k16.row.col.f32.f16.f16.f32 " \
                 "{%0,%1,%2,%3}, {%4,%5,%6,%7}, {%8,%9}, {%0,%1,%2,%3};" \
                 : "+f"((AC)[0]), "+f"((AC)[1]), "+f"((AC)[2]), "+f"((AC)[3]) \
                 : "r"(A0), "r"(A1), "r"(A2), "r"(A3), "r"(Bv0), "r"(Bv1))

#define CP_ASYNC16(DST, SRC) \
    asm volatile("cp.async.cg.shared.global [%0], [%1], 16;" :: "r"(DST), "l"(SRC))
#define CP_COMMIT()  asm volatile("cp.async.commit_group;" ::: "memory")
#define CP_WAIT0()   asm volatile("cp.async.wait_group 0;" ::: "memory")

// ---------------------------------------------------------------------------
// Kernel 1: normalize + scale by ALPHA + transpose -> fp16 [b][n][c].
// Also zeroes g_pos/g_tot rows and the output scalar.
// ---------------------------------------------------------------------------
__global__ void normalize_kernel(const float* __restrict__ feat,
                                 float* __restrict__ out) {
    __shared__ float t[C_][33];
    __shared__ float invn[32];
    const int b = blockIdx.y, n0 = blockIdx.x * 32, tid = threadIdx.x;
    const float* fb = feat + (size_t)b * C_ * N_;

    if (tid < 32) {
        g_pos[b * N_ + n0 + tid] = 0.0f;
        g_tot[b * N_ + n0 + tid] = 0.0f;
    }
    if (b == 0 && n0 == 0 && tid == 32) out[0] = 0.0f;

    for (int idx = tid; idx < C_ * 32; idx += 256) {
        int c = idx >> 5, nl = idx & 31;
        t[c][nl] = fb[(size_t)c * N_ + n0 + nl];
    }
    __syncthreads();

    const int w = tid >> 5, lane = tid & 31;
    {
        // 4 points per warp, reduced jointly (shfl latency overlapped)
        float s[4];
        #pragma unroll
        for (int p = 0; p < 4; p++) {
            int nl = w * 4 + p;
            float v0 = t[lane][nl], v1 = t[lane + 32][nl];
            float v2 = t[lane + 64][nl], v3 = t[lane + 96][nl];
            s[p] = v0 * v0 + v1 * v1 + v2 * v2 + v3 * v3;
        }
        #pragma unroll
        for (int o = 16; o > 0; o >>= 1) {
            #pragma unroll
            for (int p = 0; p < 4; p++)
                s[p] += __shfl_xor_sync(0xffffffffu, s[p], o);
        }
        if (lane < 4) invn[w * 4 + lane] =
            ALPHA / fmaxf(sqrtf(s[lane]), EPSN);
    }
    __syncthreads();

    __half* vb = g_vh + ((size_t)b * N_ + n0) * C_;
    for (int idx = tid; idx < 32 * C_; idx += 256) {
        int nl = idx >> 7, c = idx & 127;
        vb[(size_t)nl * C_ + c] = __float2half(t[c][nl] * invn[nl]);
    }
}

// ---------------------------------------------------------------------------
// Tile copy: 128 rows x 256B global -> swizzled smem via cp.async.
// Swizzle: physical 16B-chunk = c ^ (row & 7)
// ---------------------------------------------------------------------------
__device__ __forceinline__ void cp_tile(uint32_t sbase,
                                        const __half* __restrict__ src,
                                        int tid) {
    #pragma unroll
    for (int it = 0; it < 8; it++) {
        int idx = tid + it * 256;
        int r = idx >> 4, c = idx & 15;
        uint32_t dst = sbase + (uint32_t)r * 256u + (uint32_t)((c ^ (r & 7)) << 4);
        const char* g = (const char*)src + (size_t)r * 256 + c * 16;
        CP_ASYNC16(dst, g);
    }
}

// ---------------------------------------------------------------------------
// Half-tile K-loop: 32 rows x 32 cols x K=128 into acc (2 mt x 4 ntl x 4).
// ---------------------------------------------------------------------------
__device__ __forceinline__ void khalf(float (&acc)[2][4][4],
                                      const uint32_t (&af)[2][8][4],
                                      uint32_t sB,
                                      uint32_t bRow0, int bR70,
                                      uint32_t bRow1, int bR71, int csB) {
    #pragma unroll
    for (int mt = 0; mt < 2; mt++)
        #pragma unroll
        for (int nt = 0; nt < 4; nt++)
            #pragma unroll
            for (int q = 0; q < 4; q++) acc[mt][nt][q] = 0.0f;

    #pragma unroll
    for (int k = 0; k < 8; k++) {
        uint32_t bf0[4], bf1[4];
        LDSM4(bf0[0], bf0[1], bf0[2], bf0[3],
              sB + bRow0 + (uint32_t)(((2 * k + csB) ^ bR70) << 4));
        LDSM4(bf1[0], bf1[1], bf1[2], bf1[3],
              sB + bRow1 + (uint32_t)(((2 * k + csB) ^ bR71) << 4));
        #pragma unroll
        for (int mt = 0; mt < 2; mt++) {
            MMA16816(acc[mt][0], af[mt][k][0], af[mt][k][1], af[mt][k][2],
                     af[mt][k][3], bf0[0], bf0[1]);
            MMA16816(acc[mt][1], af[mt][k][0], af[mt][k][1], af[mt][k][2],
                     af[mt][k][3], bf0[2], bf0[3]);
            MMA16816(acc[mt][2], af[mt][k][0], af[mt][k][1], af[mt][k][2],
                     af[mt][k][3], bf1[0], bf1[1]);
            MMA16816(acc[mt][3], af[mt][k][0], af[mt][k][1], af[mt][k][2],
                     af[mt][k][3], bf1[2], bf1[3]);
        }
    }
}

// ---------------------------------------------------------------------------
// Epilogue of one half-tile: exp2, diagonal removal, label masking.
// ---------------------------------------------------------------------------
__device__ __forceinline__ void epi_half(const float (&acc)[2][4][4],
                                         int i, int h,
                                         const unsigned* __restrict__ cmask,
                                         const int (&labr)[2][2],
                                         const int (&growb)[2],
                                         int warpN, int lane, int rt, int cq,
                                         float (&pos)[4], float (&tot)[4]) {
    const int coff = warpN + h * 32;
    const int lw = i * 4 + (coff >> 5);          // mask word within quarter
    const int cb = cq * 1024 + i * 128 + coff;   // in-batch column base
    const bool diagHere = (rt == cq * 8 + i);
    #pragma unroll
    for (int mt = 0; mt < 2; mt++) {
        const unsigned w0 = cmask[labr[mt][0] * 32 + lw];
        const unsigned w1 = cmask[labr[mt][1] * 32 + lw];
        const int g0 = growb[mt], g1 = growb[mt] + 8;
        float t0 = 0.f, t1 = 0.f, p0 = 0.f, p1 = 0.f;
        #pragma unroll
        for (int ntl = 0; ntl < 4; ntl++) {
            const int sh = ntl * 8 + 2 * (lane & 3);
            const unsigned b0 = w0 >> sh;
            const unsigned b1 = w1 >> sh;
            float e00 = ex2f(acc[mt][ntl][0]);
            float e01 = ex2f(acc[mt][ntl][1]);
            float e10 = ex2f(acc[mt][ntl][2]);
            float e11 = ex2f(acc[mt][ntl][3]);
            if (diagHere) {
                const int gc = cb + ntl * 8 + 2 * (lane & 3);
                if (g0 == gc)     e00 = 0.f;
                if (g0 == gc + 1) e01 = 0.f;
                if (g1 == gc)     e10 = 0.f;
                if (g1 == gc + 1) e11 = 0.f;
            }
            t0 += e00 + e01;
            t1 += e10 + e11;
            p0 += ((b0 & 1u) ? e00 : 0.f) + ((b0 & 2u) ? e01 : 0.f);
            p1 += ((b1 & 1u) ? e10 : 0.f) + ((b1 & 2u) ? e11 : 0.f);
        }
        tot[mt * 2 + 0] += t0;  tot[mt * 2 + 1] += t1;
        pos[mt * 2 + 0] += p0;  pos[mt * 2 + 1] += p1;
    }
}

// ---------------------------------------------------------------------------
// Kernel 2: persistent HMMA GEMM + antiphase-pipelined exp2/mask epilogue.
// Unit u: b = u>>7, rt = (u>>2)&31, cq = u&3. 128 rows x 1024 cols per unit.
// SMSP-pair warps (wid, wid+4) run complementary K/E orders so one is
// always feeding the tensor pipe while the other runs MUFU/FMA epilogue.
// Dyn smem: A 32K | B0 32K | B1 32K | cmask 2K | posS 1K | totS 1K
// ---------------------------------------------------------------------------
#define SM_B0    32768
#define SM_B1    65536
#define SM_CMASK 98304
#define SM_POSS  (SM_CMASK + 2048)
#define SM_TOTS  (SM_POSS + 1024)
#define SM_DYN   (SM_TOTS + 1024)

__global__ void __launch_bounds__(256, 1)
loss_kernel(const int* __restrict__ labels) {
    extern __shared__ char sm[];
    const int tid = threadIdx.x, wid = tid >> 5, lane = tid & 31;

    unsigned* cmask = (unsigned*)(sm + SM_CMASK);   // [16 classes][32 words]
    float* posS = (float*)(sm + SM_POSS);           // [128][2]
    float* totS = (float*)(sm + SM_TOTS);

    const uint32_t sA  = smem_u32(sm);
    const uint32_t sB0 = smem_u32(sm + SM_B0);
    const uint32_t sB1 = smem_u32(sm + SM_B1);

    const int warpM = (wid & 3) * 32;
    const int warpN = (wid >> 2) * 64;
    const int par   = wid >> 2;     // SMSP-pair parity (warps w and w+4)

    // ldmatrix per-lane address components
    const int rA  = warpM + (lane & 15);
    const int csA = lane >> 4;
    const int rBl = (lane & 7) + ((lane & 16) >> 1);
    const int csB = (lane >> 3) & 1;

    uint32_t bRow[4];
    int bR7[4];
    #pragma unroll
    for (int np = 0; np < 4; np++) {
        int row = warpN + np * 16 + rBl;
        bRow[np] = (uint32_t)row * 256u;
        bR7[np] = row & 7;
    }

    int u = blockIdx.x;
    if (u < NU) {   // prologue loads for first unit
        const int b = u >> 7, rt = (u >> 2) & 31, cq = u & 3;
        const __half* vb = g_vh + (size_t)b * N_ * C_;
        cp_tile(sA,  vb + (size_t)(rt * TM) * C_, tid);
        cp_tile(sB0, vb + (size_t)(cq * 1024) * C_, tid);
        CP_COMMIT();
    }

    while (u < NU) {
        const int b = u >> 7, rt = (u >> 2) & 31, cq = u & 3;
        const int un = u + gridDim.x;
        const int* lb = labels + b * N_;
        const __half* vb = g_vh + (size_t)b * N_ * C_;

        CP_WAIT0();
        __syncthreads();    // A + B0 ready; prev unit fully done

        // per-class column bitmasks for this quarter (32 words per class)
        {
            int labv[4];
            #pragma unroll
            for (int i = 0; i < 4; i++)
                labv[i] = lb[cq * 1024 + (wid * 4 + i) * 32 + lane];
            #pragma unroll
            for (int i = 0; i < 4; i++)
                #pragma unroll
                for (int c = 0; c < 16; c++) {
                    unsigned m = __ballot_sync(0xffffffffu, labv[i] == c);
                    if (lane == c) cmask[c * 32 + wid * 4 + i] = m;
                }
        }

        // this thread's accumulator-row identities (in-batch rows)
        int growb[2], labr[2][2];
        #pragma unroll
        for (int mt = 0; mt < 2; mt++) {
            growb[mt] = rt * TM + warpM + mt * 16 + (lane >> 2);
            labr[mt][0] = lb[growb[mt]];
            labr[mt][1] = lb[growb[mt] + 8];
        }

        // A fragments cached in registers for the whole unit
        uint32_t af[2][8][4];
        #pragma unroll
        for (int mt = 0; mt < 2; mt++) {
            int row = rA + mt * 16;
            uint32_t base = sA + (uint32_t)row * 256u;
            int r7 = row & 7;
            #pragma unroll
            for (int k = 0; k < 8; k++) {
                uint32_t addr = base + (uint32_t)(((2 * k + csA) ^ r7) << 4);
                LDSM4(af[mt][k][0], af[mt][k][1], af[mt][k][2], af[mt][k][3],
                      addr);
            }
        }
        __syncthreads();    // cmask visible everywhere

        float pos[4] = {0.f, 0.f, 0.f, 0.f};
        float tot[4] = {0.f, 0.f, 0.f, 0.f};
        float acc0[2][4][4], acc1[2][4][4];

        for (int i = 0; i < IPU; i++) {
            const uint32_t sB = (i & 1) ? sB1 : sB0;
            // prefetch next tile (or next unit's A+B0 on the last iter)
            if (i < IPU - 1) {
                cp_tile(((i + 1) & 1) ? sB1 : sB0,
                        vb + (size_t)(cq * 1024 + (i + 1) * TN) * C_, tid);
                CP_COMMIT();
            } else if (un < NU) {
                const int bn = un >> 7, rtn = (un >> 2) & 31, cqn = un & 3;
                const __half* vbn = g_vh + (size_t)bn * N_ * C_;
                cp_tile(sA,  vbn + (size_t)(rtn * TM) * C_, tid);
                cp_tile(sB0, vbn + (size_t)(cqn * 1024) * C_, tid);
                CP_COMMIT();
            }

            // Antiphase K/E schedules per SMSP-pair parity.
            if (par == 0) {
                // K0(i), E1(i-1), K1(i), E0(i)
                khalf(acc0, af, sB, bRow[0], bR7[0], bRow[1], bR7[1], csB);
                if (i > 0)
                    epi_half(acc1, i - 1, 1, cmask, labr, growb, warpN, lane,
                             rt, cq, pos, tot);
                khalf(acc1, af, sB, bRow[2], bR7[2], bRow[3], bR7[3], csB);
                epi_half(acc0, i, 0, cmask, labr, growb, warpN, lane,
                         rt, cq, pos, tot);
            } else {
                // E1(i-1), K0(i), E0(i), K1(i)
                if (i > 0)
                    epi_half(acc1, i - 1, 1, cmask, labr, growb, warpN, lane,
                             rt, cq, pos, tot);
                khalf(acc0, af, sB, bRow[0], bR7[0], bRow[1], bR7[1], csB);
                epi_half(acc0, i, 0, cmask, labr, growb, warpN, lane,
                         rt, cq, pos, tot);
                khalf(acc1, af, sB, bRow[2], bR7[2], bRow[3], bR7[3], csB);
            }

            CP_WAIT0();
            __syncthreads();
        }
        // flush pending last half
        epi_half(acc1, IPU - 1, 1, cmask, labr, growb, warpN, lane,
                 rt, cq, pos, tot);

        // reduce 4 lanes sharing each row, merge 2 N-warps, atomic to global
        #pragma unroll
        for (int q = 0; q < 4; q++) {
            pos[q] += __shfl_xor_sync(0xffffffffu, pos[q], 1);
            pos[q] += __shfl_xor_sync(0xffffffffu, pos[q], 2);
            tot[q] += __shfl_xor_sync(0xffffffffu, tot[q], 1);
            tot[q] += __shfl_xor_sync(0xffffffffu, tot[q], 2);
        }
        const int widN = wid >> 2;
        if ((lane & 3) == 0) {
            #pragma unroll
            for (int mt = 0; mt < 2; mt++) {
                int rl = warpM + mt * 16 + (lane >> 2);
                posS[rl * 2 + widN]       = pos[mt * 2 + 0];
                totS[rl * 2 + widN]       = tot[mt * 2 + 0];
                posS[(rl + 8) * 2 + widN] = pos[mt * 2 + 1];
                totS[(rl + 8) * 2 + widN] = tot[mt * 2 + 1];
            }
        }
        __syncthreads();
        if (tid < TM) {
            float P = posS[tid * 2] + posS[tid * 2 + 1];
            float T = totS[tid * 2] + totS[tid * 2 + 1];
            int gr = b * N_ + rt * TM + tid;
            atomicAdd(&g_pos[gr], P);
            atomicAdd(&g_tot[gr], T);
        }
        u = un;
    }
}

// ---------------------------------------------------------------------------
// Kernel 3: finalize — dev = log(T) - log(P) per row, mean into out.
// ---------------------------------------------------------------------------
__global__ void finalize_kernel(float* __restrict__ out) {
    __shared__ float ws[8];
    const int idx = blockIdx.x * 256 + threadIdx.x;
    const int lane = threadIdx.x & 31, wid = threadIdx.x >> 5;
    float dev = __logf(g_tot[idx]) - __logf(g_pos[idx]);
    #pragma unroll
    for (int o = 16; o > 0; o >>= 1) dev += __shfl_xor_sync(0xffffffffu, dev, o);
    if (lane == 0) ws[wid] = dev;
    __syncthreads();
    if (threadIdx.x == 0) {
        float s = 0.0f;
        #pragma unroll
        for (int w = 0; w < 8; w++) s += ws[w];
        atomicAdd(out, s * (1.0f / ((float)B_ * (float)N_)));
    }
}

// ---------------------------------------------------------------------------
// Launch
// ---------------------------------------------------------------------------
extern "C" void kernel_launch(void* const* d_in, const int* in_sizes, int n_in,
                              void* d_out, int out_size) {
    const float* feat   = (const float*)d_in[0];
    const int*   labels = (const int*)d_in[1];
    float*       out    = (float*)d_out;

    dim3 gn(N_ / 32, B_);
    normalize_kernel<<<gn, 256>>>(feat, out);

    cudaFuncSetAttribute(loss_kernel,
                         cudaFuncAttributeMaxDynamicSharedMemorySize, SM_DYN);
    loss_kernel<<<GRIDP, 256, SM_DYN>>>(labels);

    finalize_kernel<<<(B_ * N_) / 256, 256>>>(out);
}

// round 16
// speedup vs baseline: 1.4659x; 1.0661x over previous
#include <cuda_runtime.h>
#include <cuda_fp16.h>
#include <math.h>
#include <stdint.h>

// ---------------------------------------------------------------------------
// Problem constants
// ---------------------------------------------------------------------------
#define B_   8
#define C_   128
#define N_   4096
#define EPSN 1e-12f
// exp(x/0.1) = 2^(x * 10*log2(e)); fold sqrt of scale into both vectors.
#define ALPHA 3.7982826f          // sqrt(14.4269504089)

#define TM   128                  // rows per unit
#define TN   128                  // cols per iteration tile
#define IPU  8                    // iterations (col tiles) per unit
#define NU   (B_ * 32 * 4)        // 1024 work units
#define GRIDP 148                 // persistent CTAs

// Scratch: normalized+scaled features fp16, [b][n][c] (8 MB)
__device__ __align__(16) __half g_vh[(size_t)B_ * N_ * C_];
// Per-row partial sums (merged across col-quarter units)
__device__ float g_pos[B_ * N_];
__device__ float g_tot[B_ * N_];

// ---------------------------------------------------------------------------
// Helpers
// ---------------------------------------------------------------------------
__device__ __forceinline__ uint32_t smem_u32(const void* p) {
    uint32_t a;
    asm("{ .reg .u64 t; cvta.to.shared.u64 t, %1; cvt.u32.u64 %0, t; }"
        : "=r"(a) : "l"(p));
    return a;
}

__device__ __forceinline__ float ex2f(float x) {
    float y;
    asm("ex2.approx.f32 %0, %1;" : "=f"(y) : "f"(x));
    return y;
}

// pack two f32 into f16x2: low half = lo, high half = hi
__device__ __forceinline__ uint32_t pack16x2(float lo, float hi) {
    uint32_t r;
    asm("cvt.rn.f16x2.f32 %0, %1, %2;" : "=r"(r) : "f"(hi), "f"(lo));
    return r;
}

#define LDSM4(R0, R1, R2, R3, ADDR) \
    asm volatile("ldmatrix.sync.aligned.m8n8.x4.shared.b16 {%0,%1,%2,%3}, [%4];" \
                 : "=r"(R0), "=r"(R1), "=r"(R2), "=r"(R3) : "r"(ADDR))

#define MMA16816(AC, A0, A1, A2, A3, Bv0, Bv1) \
    asm volatile("mma.sync.aligned.m16n8k16.row.col.f32.f16.f16.f32 " \
                 "{%0,%1,%2,%3}, {%4,%5,%6,%7}, {%8,%9}, {%0,%1,%2,%3};" \
                 : "+f"((AC)[0]), "+f"((AC)[1]), "+f"((AC)[2]), "+f"((AC)[3]) \
                 : "r"(A0), "r"(A1), "r"(A2), "r"(A3), "r"(Bv0), "r"(Bv1))

#define CP_ASYNC16(DST, SRC) \
    asm volatile("cp.async.cg.shared.global [%0], [%1], 16;" :: "r"(DST), "l"(SRC))
#define CP_COMMIT()  asm volatile("cp.async.commit_group;" ::: "memory")
#define CP_WAIT0()   asm volatile("cp.async.wait_group 0;" ::: "memory")

// ---------------------------------------------------------------------------
// Kernel 1: normalize + scale by ALPHA + transpose -> fp16 [b][n][c].
// Also zeroes g_pos/g_tot rows and the output scalar.
// ---------------------------------------------------------------------------
__global__ void normalize_kernel(const float* __restrict__ feat,
                                 float* __restrict__ out) {
    __shared__ float t[C_][33];
    __shared__ float invn[32];
    const int b = blockIdx.y, n0 = blockIdx.x * 32, tid = threadIdx.x;
    const float* fb = feat + (size_t)b * C_ * N_;

    if (tid < 32) {
        g_pos[b * N_ + n0 + tid] = 0.0f;
        g_tot[b * N_ + n0 + tid] = 0.0f;
    }
    if (b == 0 && n0 == 0 && tid == 32) out[0] = 0.0f;

    for (int idx = tid; idx < C_ * 32; idx += 256) {
        int c = idx >> 5, nl = idx & 31;
        t[c][nl] = fb[(size_t)c * N_ + n0 + nl];
    }
    __syncthreads();

    const int w = tid >> 5, lane = tid & 31;
    {
        float s[4];
        #pragma unroll
        for (int p = 0; p < 4; p++) {
            int nl = w * 4 + p;
            float v0 = t[lane][nl], v1 = t[lane + 32][nl];
            float v2 = t[lane + 64][nl], v3 = t[lane + 96][nl];
            s[p] = v0 * v0 + v1 * v1 + v2 * v2 + v3 * v3;
        }
        #pragma unroll
        for (int o = 16; o > 0; o >>= 1) {
            #pragma unroll
            for (int p = 0; p < 4; p++)
                s[p] += __shfl_xor_sync(0xffffffffu, s[p], o);
        }
        if (lane < 4) invn[w * 4 + lane] =
            ALPHA / fmaxf(sqrtf(s[lane]), EPSN);
    }
    __syncthreads();

    __half* vb = g_vh + ((size_t)b * N_ + n0) * C_;
    for (int idx = tid; idx < 32 * C_; idx += 256) {
        int nl = idx >> 7, c = idx & 127;
        vb[(size_t)nl * C_ + c] = __float2half(t[c][nl] * invn[nl]);
    }
}

// ---------------------------------------------------------------------------
// Tile copy: 128 rows x 256B global -> swizzled smem via cp.async.
// ---------------------------------------------------------------------------
__device__ __forceinline__ void cp_tile(uint32_t sbase,
                                        const __half* __restrict__ src,
                                        int tid) {
    #pragma unroll
    for (int it = 0; it < 8; it++) {
        int idx = tid + it * 256;
        int r = idx >> 4, c = idx & 15;
        uint32_t dst = sbase + (uint32_t)r * 256u + (uint32_t)((c ^ (r & 7)) << 4);
        const char* g = (const char*)src + (size_t)r * 256 + c * 16;
        CP_ASYNC16(dst, g);
    }
}

// ---------------------------------------------------------------------------
// Half-tile K-loop: 32 rows x 32 cols x K=128 into acc (2 mt x 4 ntl x 4).
// ---------------------------------------------------------------------------
__device__ __forceinline__ void khalf(float (&acc)[2][4][4],
                                      const uint32_t (&af)[2][8][4],
                                      uint32_t sB,
                                      uint32_t bRow0, int bR70,
                                      uint32_t bRow1, int bR71, int csB) {
    #pragma unroll
    for (int mt = 0; mt < 2; mt++)
        #pragma unroll
        for (int nt = 0; nt < 4; nt++)
            #pragma unroll
            for (int q = 0; q < 4; q++) acc[mt][nt][q] = 0.0f;

    #pragma unroll
    for (int k = 0; k < 8; k++) {
        uint32_t bf0[4], bf1[4];
        LDSM4(bf0[0], bf0[1], bf0[2], bf0[3],
              sB + bRow0 + (uint32_t)(((2 * k + csB) ^ bR70) << 4));
        LDSM4(bf1[0], bf1[1], bf1[2], bf1[3],
              sB + bRow1 + (uint32_t)(((2 * k + csB) ^ bR71) << 4));
        #pragma unroll
        for (int mt = 0; mt < 2; mt++) {
            MMA16816(acc[mt][0], af[mt][k][0], af[mt][k][1], af[mt][k][2],
                     af[mt][k][3], bf0[0], bf0[1]);
            MMA16816(acc[mt][1], af[mt][k][0], af[mt][k][1], af[mt][k][2],
                     af[mt][k][3], bf0[2], bf0[3]);
            MMA16816(acc[mt][2], af[mt][k][0], af[mt][k][1], af[mt][k][2],
                     af[mt][k][3], bf1[0], bf1[1]);
            MMA16816(acc[mt][3], af[mt][k][0], af[mt][k][1], af[mt][k][2],
                     af[mt][k][3], bf1[2], bf1[3]);
        }
    }
}

// ---------------------------------------------------------------------------
// Epilogue of one half-tile via tensor reduction:
//   e = exp2(acc) (diag-zeroed), packed fp16 P-fragments (acc layout == A
//   layout), classum[mt][nt] += P @ M where M[j][c] = (label_j == c),
//   built from cmask ballot words.
// ---------------------------------------------------------------------------
__device__ __forceinline__ void epi_half(const float (&acc)[2][4][4],
                                         int i, int h,
                                         const unsigned* __restrict__ cmask,
                                         const int (&growb)[2],
                                         int warpN, int lane, int rt, int cq,
                                         float (&cs)[2][2][4]) {
    const int t = lane & 3;
    const int g = lane >> 2;
    const int lw = i * 4 + ((warpN + h * 32) >> 5);
    const bool diagHere = (rt == cq * 8 + i);
    const int cb = cq * 1024 + i * 128 + warpN + h * 32;

    // pack P fragments (EX2 + diag zero + cvt), scoped to limit liveness
    uint32_t pa[2][2][4];       // [mt][ks][a0..a3]
    #pragma unroll
    for (int mt = 0; mt < 2; mt++) {
        const int g0 = growb[mt], g1 = growb[mt] + 8;
        #pragma unroll
        for (int ks = 0; ks < 2; ks++) {
            #pragma unroll
            for (int hb = 0; hb < 2; hb++) {
                const int ntl = 2 * ks + hb;
                float e0 = ex2f(acc[mt][ntl][0]);
                float e1 = ex2f(acc[mt][ntl][1]);
                float e2 = ex2f(acc[mt][ntl][2]);
                float e3 = ex2f(acc[mt][ntl][3]);
                if (diagHere) {
                    const int gc = cb + ntl * 8 + 2 * t;
                    if (g0 == gc)     e0 = 0.f;
                    if (g0 == gc + 1) e1 = 0.f;
                    if (g1 == gc)     e2 = 0.f;
                    if (g1 == gc + 1) e3 = 0.f;
                }
                pa[mt][ks][hb * 2 + 0] = pack16x2(e0, e1);
                pa[mt][ks][hb * 2 + 1] = pack16x2(e2, e3);
            }
        }
    }

    // B mask fragments from cmask words (classes g and g+8)
    const unsigned wlo = cmask[g * 32 + lw];
    const unsigned whi = cmask[(g + 8) * 32 + lw];
    uint32_t bm[2][2][2];       // [ks][nt][reg]
    #pragma unroll
    for (int ks = 0; ks < 2; ks++) {
        const unsigned slo = wlo >> (16 * ks + 2 * t);
        const unsigned shi = whi >> (16 * ks + 2 * t);
        bm[ks][0][0] = ((slo & 1u) ? 0x3C00u : 0u)
                     | ((slo & 2u) ? 0x3C000000u : 0u);
        bm[ks][0][1] = (((slo >> 8) & 1u) ? 0x3C00u : 0u)
                     | (((slo >> 8) & 2u) ? 0x3C000000u : 0u);
        bm[ks][1][0] = ((shi & 1u) ? 0x3C00u : 0u)
                     | ((shi & 2u) ? 0x3C000000u : 0u);
        bm[ks][1][1] = (((shi >> 8) & 1u) ? 0x3C00u : 0u)
                     | (((shi >> 8) & 2u) ? 0x3C000000u : 0u);
    }

    // reduction MMAs: classum += P @ M   (K=32 -> 2 k-steps, N=16 -> 2 nt)
    #pragma unroll
    for (int mt = 0; mt < 2; mt++)
        #pragma unroll
        for (int ks = 0; ks < 2; ks++) {
            MMA16816(cs[mt][0], pa[mt][ks][0], pa[mt][ks][1], pa[mt][ks][2],
                     pa[mt][ks][3], bm[ks][0][0], bm[ks][0][1]);
            MMA16816(cs[mt][1], pa[mt][ks][0], pa[mt][ks][1], pa[mt][ks][2],
                     pa[mt][ks][3], bm[ks][1][0], bm[ks][1][1]);
        }
}

// ---------------------------------------------------------------------------
// Kernel 2: persistent HMMA GEMM + tensor-reduced epilogue.
// Unit u: b = u>>7, rt = (u>>2)&31, cq = u&3. 128 rows x 1024 cols per unit.
// Dyn smem: A 32K | B0 32K | B1 32K | cmask 2K | posS 1K | totS 1K
// ---------------------------------------------------------------------------
#define SM_B0    32768
#define SM_B1    65536
#define SM_CMASK 98304
#define SM_POSS  (SM_CMASK + 2048)
#define SM_TOTS  (SM_POSS + 1024)
#define SM_DYN   (SM_TOTS + 1024)

__global__ void __launch_bounds__(256, 1)
loss_kernel(const int* __restrict__ labels) {
    extern __shared__ char sm[];
    const int tid = threadIdx.x, wid = tid >> 5, lane = tid & 31;

    unsigned* cmask = (unsigned*)(sm + SM_CMASK);   // [16 classes][32 words]
    float* posS = (float*)(sm + SM_POSS);           // [128][2]
    float* totS = (float*)(sm + SM_TOTS);

    const uint32_t sA  = smem_u32(sm);
    const uint32_t sB0 = smem_u32(sm + SM_B0);
    const uint32_t sB1 = smem_u32(sm + SM_B1);

    const int warpM = (wid & 3) * 32;
    const int warpN = (wid >> 2) * 64;
    const int par   = wid >> 2;     // SMSP-pair parity

    // ldmatrix per-lane address components
    const int rA  = warpM + (lane & 15);
    const int csA = lane >> 4;
    const int rBl = (lane & 7) + ((lane & 16) >> 1);
    const int csB = (lane >> 3) & 1;

    uint32_t bRow[4];
    int bR7[4];
    #pragma unroll
    for (int np = 0; np < 4; np++) {
        int row = warpN + np * 16 + rBl;
        bRow[np] = (uint32_t)row * 256u;
        bR7[np] = row & 7;
    }

    int u = blockIdx.x;
    if (u < NU) {   // prologue loads for first unit
        const int b = u >> 7, rt = (u >> 2) & 31, cq = u & 3;
        const __half* vb = g_vh + (size_t)b * N_ * C_;
        cp_tile(sA,  vb + (size_t)(rt * TM) * C_, tid);
        cp_tile(sB0, vb + (size_t)(cq * 1024) * C_, tid);
        CP_COMMIT();
    }

    while (u < NU) {
        const int b = u >> 7, rt = (u >> 2) & 31, cq = u & 3;
        const int un = u + gridDim.x;
        const int* lb = labels + b * N_;
        const __half* vb = g_vh + (size_t)b * N_ * C_;

        CP_WAIT0();
        __syncthreads();    // A + B0 ready; prev unit fully done

        // per-class column bitmasks for this quarter (32 words per class)
        {
            int labv[4];
            #pragma unroll
            for (int i = 0; i < 4; i++)
                labv[i] = lb[cq * 1024 + (wid * 4 + i) * 32 + lane];
            #pragma unroll
            for (int i = 0; i < 4; i++)
                #pragma unroll
                for (int c = 0; c < 16; c++) {
                    unsigned m = __ballot_sync(0xffffffffu, labv[i] == c);
                    if (lane == c) cmask[c * 32 + wid * 4 + i] = m;
                }
        }

        // this thread's accumulator-row identities (in-batch rows)
        int growb[2], labr[2][2];
        #pragma unroll
        for (int mt = 0; mt < 2; mt++) {
            growb[mt] = rt * TM + warpM + mt * 16 + (lane >> 2);
            labr[mt][0] = lb[growb[mt]];
            labr[mt][1] = lb[growb[mt] + 8];
        }

        // A fragments cached in registers for the whole unit
        uint32_t af[2][8][4];
        #pragma unroll
        for (int mt = 0; mt < 2; mt++) {
            int row = rA + mt * 16;
            uint32_t base = sA + (uint32_t)row * 256u;
            int r7 = row & 7;
            #pragma unroll
            for (int k = 0; k < 8; k++) {
                uint32_t addr = base + (uint32_t)(((2 * k + csA) ^ r7) << 4);
                LDSM4(af[mt][k][0], af[mt][k][1], af[mt][k][2], af[mt][k][3],
                      addr);
            }
        }
        __syncthreads();    // cmask visible everywhere

        // per-unit class-sum accumulators (rows x 16 classes, fp32)
        float cs[2][2][4];
        #pragma unroll
        for (int mt = 0; mt < 2; mt++)
            #pragma unroll
            for (int nt = 0; nt < 2; nt++)
                #pragma unroll
                for (int q = 0; q < 4; q++) cs[mt][nt][q] = 0.0f;

        float acc0[2][4][4], acc1[2][4][4];

        for (int i = 0; i < IPU; i++) {
            const uint32_t sB = (i & 1) ? sB1 : sB0;
            if (i < IPU - 1) {
                cp_tile(((i + 1) & 1) ? sB1 : sB0,
                        vb + (size_t)(cq * 1024 + (i + 1) * TN) * C_, tid);
                CP_COMMIT();
            } else if (un < NU) {
                const int bn = un >> 7, rtn = (un >> 2) & 31, cqn = un & 3;
                const __half* vbn = g_vh + (size_t)bn * N_ * C_;
                cp_tile(sA,  vbn + (size_t)(rtn * TM) * C_, tid);
                cp_tile(sB0, vbn + (size_t)(cqn * 1024) * C_, tid);
                CP_COMMIT();
            }

            if (par == 0) {
                // K0(i), E1(i-1), K1(i), E0(i)
                khalf(acc0, af, sB, bRow[0], bR7[0], bRow[1], bR7[1], csB);
                if (i > 0)
                    epi_half(acc1, i - 1, 1, cmask, growb, warpN, lane,
                             rt, cq, cs);
                khalf(acc1, af, sB, bRow[2], bR7[2], bRow[3], bR7[3], csB);
                epi_half(acc0, i, 0, cmask, growb, warpN, lane, rt, cq, cs);
            } else {
                // E1(i-1), K0(i), E0(i), K1(i)
                if (i > 0)
                    epi_half(acc1, i - 1, 1, cmask, growb, warpN, lane,
                             rt, cq, cs);
                khalf(acc0, af, sB, bRow[0], bR7[0], bRow[1], bR7[1], csB);
                epi_half(acc0, i, 0, cmask, growb, warpN, lane, rt, cq, cs);
                khalf(acc1, af, sB, bRow[2], bR7[2], bRow[3], bR7[3], csB);
            }

            CP_WAIT0();
            __syncthreads();
        }
        // flush pending last half
        epi_half(acc1, IPU - 1, 1, cmask, growb, warpN, lane, rt, cq, cs);

        // per-unit extraction: tot = sum over all 16 classes; pos = own class
        float pos[4], tot[4];
        {
            const int t2 = 2 * (lane & 3);
            #pragma unroll
            for (int mt = 0; mt < 2; mt++) {
                tot[mt * 2 + 0] = cs[mt][0][0] + cs[mt][0][1]
                                + cs[mt][1][0] + cs[mt][1][1];
                tot[mt * 2 + 1] = cs[mt][0][2] + cs[mt][0][3]
                                + cs[mt][1][2] + cs[mt][1][3];
                const int L0 = labr[mt][0], L1 = labr[mt][1];
                float p0 = 0.f, p1 = 0.f;
                #pragma unroll
                for (int nt = 0; nt < 2; nt++) {
                    const int cb2 = nt * 8 + t2;
                    p0 += (L0 == cb2)     ? cs[mt][nt][0] : 0.f;
                    p0 += (L0 == cb2 + 1) ? cs[mt][nt][1] : 0.f;
                    p1 += (L1 == cb2)     ? cs[mt][nt][2] : 0.f;
                    p1 += (L1 == cb2 + 1) ? cs[mt][nt][3] : 0.f;
                }
                pos[mt * 2 + 0] = p0;
                pos[mt * 2 + 1] = p1;
            }
        }

        // reduce 4 lanes sharing each row, merge 2 N-warps, atomic to global
        #pragma unroll
        for (int q = 0; q < 4; q++) {
            pos[q] += __shfl_xor_sync(0xffffffffu, pos[q], 1);
            pos[q] += __shfl_xor_sync(0xffffffffu, pos[q], 2);
            tot[q] += __shfl_xor_sync(0xffffffffu, tot[q], 1);
            tot[q] += __shfl_xor_sync(0xffffffffu, tot[q], 2);
        }
        const int widN = wid >> 2;
        if ((lane & 3) == 0) {
            #pragma unroll
            for (int mt = 0; mt < 2; mt++) {
                int rl = warpM + mt * 16 + (lane >> 2);
                posS[rl * 2 + widN]       = pos[mt * 2 + 0];
                totS[rl * 2 + widN]       = tot[mt * 2 + 0];
                posS[(rl + 8) * 2 + widN] = pos[mt * 2 + 1];
                totS[(rl + 8) * 2 + widN] = tot[mt * 2 + 1];
            }
        }
        __syncthreads();
        if (tid < TM) {
            float P = posS[tid * 2] + posS[tid * 2 + 1];
            float T = totS[tid * 2] + totS[tid * 2 + 1];
            int gr = b * N_ + rt * TM + tid;
            atomicAdd(&g_pos[gr], P);
            atomicAdd(&g_tot[gr], T);
        }
        u = un;
    }
}

// ---------------------------------------------------------------------------
// Kernel 3: finalize — dev = log(T) - log(P) per row, mean into out.
// ---------------------------------------------------------------------------
__global__ void finalize_kernel(float* __restrict__ out) {
    __shared__ float ws[8];
    const int idx = blockIdx.x * 256 + threadIdx.x;
    const int lane = threadIdx.x & 31, wid = threadIdx.x >> 5;
    float dev = __logf(g_tot[idx]) - __logf(g_pos[idx]);
    #pragma unroll
    for (int o = 16; o > 0; o >>= 1) dev += __shfl_xor_sync(0xffffffffu, dev, o);
    if (lane == 0) ws[wid] = dev;
    __syncthreads();
    if (threadIdx.x == 0) {
        float s = 0.0f;
        #pragma unroll
        for (int w = 0; w < 8; w++) s += ws[w];
        atomicAdd(out, s * (1.0f / ((float)B_ * (float)N_)));
    }
}

// ---------------------------------------------------------------------------
// Launch
// ---------------------------------------------------------------------------
extern "C" void kernel_launch(void* const* d_in, const int* in_sizes, int n_in,
                              void* d_out, int out_size) {
    const float* feat   = (const float*)d_in[0];
    const int*   labels = (const int*)d_in[1];
    float*       out    = (float*)d_out;

    dim3 gn(N_ / 32, B_);
    normalize_kernel<<<gn, 256>>>(feat, out);

    cudaFuncSetAttribute(loss_kernel,
                         cudaFuncAttributeMaxDynamicSharedMemorySize, SM_DYN);
    loss_kernel<<<GRIDP, 256, SM_DYN>>>(labels);

    finalize_kernel<<<(B_ * N_) / 256, 256>>>(out);
}